// round 8
// baseline (speedup 1.0000x reference)
#include <cuda_runtime.h>
#include <math_constants.h>
#include <cstdint>

// out = softmax(p1 @ p2^T * sqrt(N2)) @ p2 ; N1=N2=8192, D=128, fp32.
//
// Round 8: CUDA-core f32x2 kernel, register-pressure + pipeline fix.
//  * BN=32: acc2 halved to 16 regs -> ~100 live regs, no spills at 2 CTA/SM
//  * P stored packed-duplicated {p,p}: GEMM2 loses all PACK2 ALU
//  * deferred l-sum (lane-local, one butterfly at kernel end)
//  * ex2.approx.ftz.f32 for all exponentials
//  * double-buffered KV with cp.async.cg prefetch (load overlaps compute)
//  * split-KV x2 + merge kernel (unchanged)

#define N1v 8192
#define N2v 8192
#define DD  128
#define BM  64
#define BN  32
#define NKV_HALF 4096
#define NT  (NKV_HALF / BN)     // 128 tiles per CTA
#define QPAD 132                // q/kv row stride (floats)
#define PPAD 68                 // sp row stride (floats): 64 dup floats + pad
#define NTHREADS 256
#define C2F 130.57784f          // sqrt(8192) * log2(e)

// smem layout (floats)
#define SQ_OFF   0
#define SKV_OFF  (BM * QPAD)                    // 2 buffers of [BN][QPAD]
#define SP_OFF   (SKV_OFF + 2 * BN * QPAD)
#define SMEM_FLOATS (SP_OFF + BM * PPAD)

// packed f32x2 ops (ptxas never auto-fuses these from C++)
#define FMA2(d, a, b) asm("fma.rn.f32x2 %0, %1, %2, %0;" : "+l"(d) : "l"(a), "l"(b))
#define MUL2(d, s)    asm("mul.rn.f32x2 %0, %0, %1;"     : "+l"(d) : "l"(s))
#define PACK2(d, x, y) asm("mov.b64 %0, {%1, %2};" : "=l"(d) : "f"(x), "f"(y))
#define UNPACK2(lo, hi, v) asm("mov.b64 {%0, %1}, %2;" : "=f"(lo), "=f"(hi) : "l"(v))

__device__ __forceinline__ float ex2(float x) {
    float r;
    asm("ex2.approx.ftz.f32 %0, %1;" : "=f"(r) : "f"(x));
    return r;
}
__device__ __forceinline__ uint32_t smem_u32(const void* p) {
    uint32_t a;
    asm("{ .reg .u64 t; cvta.to.shared.u64 t, %1; cvt.u32.u64 %0, t; }" : "=r"(a) : "l"(p));
    return a;
}
__device__ __forceinline__ void cp_async16(uint32_t dst, const void* src) {
    asm volatile("cp.async.cg.shared.global [%0], [%1], 16;" :: "r"(dst), "l"(src) : "memory");
}
#define CP_COMMIT() asm volatile("cp.async.commit_group;" ::: "memory")
#define CP_WAIT0()  asm volatile("cp.async.wait_group 0;" ::: "memory")

// ---- split-KV scratch (static device globals: no runtime allocation) ----
__device__ float g_opart[2][N1v][DD];
__device__ float g_m[2][N1v];
__device__ float g_l[2][N1v];

__global__ __launch_bounds__(NTHREADS, 2)
void attn_fwd_kernel(const float* __restrict__ P1,
                     const float* __restrict__ P2)
{
    extern __shared__ float smem[];
    float* sq  = smem + SQ_OFF;             // [BM][QPAD]
    float* sp  = smem + SP_OFF;             // [BM][PPAD] duplicated pairs
    const uint32_t sb = smem_u32(smem);

    const int t   = threadIdx.x;
    const int mr  = t >> 4;                 // 0..15 row-group id
    const int mc  = t & 15;                 // 0..15 lane within row-group
    const int r0  = mr * 4;                 // this thread's 4 rows
    const int dcA = 4 * mc;                 // GEMM2 output cols {4mc..4mc+3}
    const int dcB = 64 + 4 * mc;            //                  {64+4mc..}
    const int qt    = blockIdx.x >> 1;
    const int half  = blockIdx.x & 1;
    const int qbase = qt * BM;
    const int kv0   = half * NKV_HALF;

    // ---- async preload: Q tile (2048 float4) + KV tile 0 (1024 float4) ----
    {
        const float4* qsrc = (const float4*)(P1 + (size_t)qbase * DD);
        #pragma unroll
        for (int i = 0; i < 8; i++) {
            int idx = t + i * NTHREADS;       // 0..2047
            int row = idx >> 5, c4 = idx & 31;
            cp_async16(sb + (uint32_t)((SQ_OFF + row * QPAD + c4 * 4) * 4), qsrc + idx);
        }
        const float4* ksrc = (const float4*)(P2 + (size_t)kv0 * DD);
        #pragma unroll
        for (int i = 0; i < 4; i++) {
            int idx = t + i * NTHREADS;       // 0..1023
            int row = idx >> 5, c4 = idx & 31;
            cp_async16(sb + (uint32_t)((SKV_OFF + row * QPAD + c4 * 4) * 4), ksrc + idx);
        }
        CP_COMMIT();
    }

    // ---- softmax state + packed O accumulators ----
    float m_run[4], l_lane[4];
    unsigned long long o2[4][4];            // 4 rows x 4 col-pairs (8 cols)
    #pragma unroll
    for (int i = 0; i < 4; i++) {
        m_run[i] = -CUDART_INF_F;
        l_lane[i] = 0.f;
        #pragma unroll
        for (int d = 0; d < 4; d++) o2[i][d] = 0ull;
    }

    for (int it = 0; it < NT; it++) {
        // tile `it` resident in buffer it&1 once wait+barrier complete
        CP_WAIT0();
        __syncthreads();   // (also: all threads done reading buffer (it+1)&1)

        // ---- prefetch tile it+1 into the other buffer ----
        if (it + 1 < NT) {
            const float4* ksrc = (const float4*)(P2 + (size_t)(kv0 + (it + 1) * BN) * DD);
            uint32_t boff = (uint32_t)((SKV_OFF + ((it + 1) & 1) * BN * QPAD) * 4);
            #pragma unroll
            for (int i = 0; i < 4; i++) {
                int idx = t + i * NTHREADS;
                int row = idx >> 5, c4 = idx & 31;
                cp_async16(sb + boff + (uint32_t)((row * QPAD + c4 * 4) * 4), ksrc + idx);
            }
        }
        CP_COMMIT();       // commit even when empty: keeps wait_group counts aligned

        const float* skv = smem + SKV_OFF + (it & 1) * BN * QPAD;

        // ---- GEMM1 (packed k-pairs): acc2[i][j] = q[r0+i] . kv[mc+16j] ----
        unsigned long long acc2[4][2];
        #pragma unroll
        for (int i = 0; i < 4; i++) {
            acc2[i][0] = 0ull;
            acc2[i][1] = 0ull;
        }
        #pragma unroll 2
        for (int k = 0; k < DD; k += 4) {
            ulonglong2 B0 = *(const ulonglong2*)&skv[mc * QPAD + k];         // broadcast
            ulonglong2 B1 = *(const ulonglong2*)&skv[(mc + 16) * QPAD + k];  // across warp
            #pragma unroll
            for (int i = 0; i < 4; i++) {
                ulonglong2 A = *(const ulonglong2*)&sq[(r0 + i) * QPAD + k];
                FMA2(acc2[i][0], A.x, B0.x);
                FMA2(acc2[i][0], A.y, B0.y);
                FMA2(acc2[i][1], A.x, B1.x);
                FMA2(acc2[i][1], A.y, B1.y);
            }
        }

        // ---- online softmax (max across 16-lane group; l deferred) ----
        #pragma unroll
        for (int i = 0; i < 4; i++) {
            float s0, s1;
            {
                float lo, hi;
                UNPACK2(lo, hi, acc2[i][0]); s0 = lo + hi;
                UNPACK2(lo, hi, acc2[i][1]); s1 = lo + hi;
            }
            float mloc = fmaxf(s0, s1) * C2F;   // log2-domain logits
            #pragma unroll
            for (int off = 1; off < 16; off <<= 1)
                mloc = fmaxf(mloc, __shfl_xor_sync(0xffffffffu, mloc, off));

            float mnew = fmaxf(m_run[i], mloc);
            float corr = ex2(m_run[i] - mnew);   // ex2(-inf)=0 first tile
            m_run[i] = mnew;

            float p0 = ex2(fmaf(s0, C2F, -mnew));
            float p1 = ex2(fmaf(s1, C2F, -mnew));
            l_lane[i] = fmaf(l_lane[i], corr, p0 + p1);   // lane-local partial l

            // store duplicated pairs {p,p} for PACK2-free GEMM2
            unsigned long long d0, d1;
            PACK2(d0, p0, p0);
            PACK2(d1, p1, p1);
            *(unsigned long long*)&sp[(r0 + i) * PPAD + 2 * mc]        = d0;
            *(unsigned long long*)&sp[(r0 + i) * PPAD + 2 * mc + 32]   = d1;

            unsigned long long corr2;
            PACK2(corr2, corr, corr);
            #pragma unroll
            for (int d = 0; d < 4; d++) MUL2(o2[i][d], corr2);
        }
        // P rows r0..r0+3 produced & consumed entirely within this 16-lane group
        __syncwarp();

        // ---- GEMM2: o2[i][.] += P[r0+i][j] * kv[j][cols], P pre-packed ----
        #pragma unroll 1
        for (int jb4 = 0; jb4 < BN; jb4 += 4) {
            ulonglong2 Pa[4], Pb[4];   // dup pairs for j = jb4..jb4+3
            #pragma unroll
            for (int i = 0; i < 4; i++) {
                const float* pr = &sp[(r0 + i) * PPAD + 2 * jb4];
                Pa[i] = *(const ulonglong2*)pr;        // j = jb4, jb4+1
                Pb[i] = *(const ulonglong2*)(pr + 4);  // j = jb4+2, jb4+3
            }
            #pragma unroll
            for (int jj = 0; jj < 4; jj++) {
                const float* vr = &skv[(jb4 + jj) * QPAD];
                ulonglong2 vA = *(const ulonglong2*)(vr + dcA);
                ulonglong2 vB = *(const ulonglong2*)(vr + dcB);
                #pragma unroll
                for (int i = 0; i < 4; i++) {
                    unsigned long long pp =
                        (jj == 0) ? Pa[i].x : (jj == 1) ? Pa[i].y
                      : (jj == 2) ? Pb[i].x : Pb[i].y;
                    FMA2(o2[i][0], pp, vA.x);
                    FMA2(o2[i][1], pp, vA.y);
                    FMA2(o2[i][2], pp, vB.x);
                    FMA2(o2[i][3], pp, vB.y);
                }
            }
        }
        // next iteration's top-of-loop __syncthreads protects skv buffer reuse
    }

    // ---- finalize l: butterfly over the 16-lane row group ----
    float l_run[4];
    #pragma unroll
    for (int i = 0; i < 4; i++) {
        float l = l_lane[i];
        #pragma unroll
        for (int off = 1; off < 16; off <<= 1)
            l += __shfl_xor_sync(0xffffffffu, l, off);
        l_run[i] = l;
    }

    // ---- epilogue: per-half normalized partial + (m,l) for the merge ----
    if (mc == 0) {
        #pragma unroll
        for (int i = 0; i < 4; i++) {
            g_m[half][qbase + r0 + i] = m_run[i];
            g_l[half][qbase + r0 + i] = l_run[i];
        }
    }
    #pragma unroll
    for (int i = 0; i < 4; i++) {
        float inv = 1.0f / l_run[i];
        float f[8];
        #pragma unroll
        for (int d = 0; d < 4; d++) {
            float lo, hi;
            UNPACK2(lo, hi, o2[i][d]);
            f[2 * d]     = lo * inv;
            f[2 * d + 1] = hi * inv;
        }
        float* dst = &g_opart[half][qbase + r0 + i][0];
        *(float4*)(dst + dcA) = make_float4(f[0], f[1], f[2], f[3]);
        *(float4*)(dst + dcB) = make_float4(f[4], f[5], f[6], f[7]);
    }
}

// combine the two KV halves:  out = (w0*o0 + w1*o1)/(w0+w1),  w = l * 2^(m-M)
__global__ void merge_kernel(float* __restrict__ out)
{
    int idx = blockIdx.x * blockDim.x + threadIdx.x;   // over 8192*128
    int row = idx >> 7;
    float m0 = g_m[0][row], m1 = g_m[1][row];
    float M  = fmaxf(m0, m1);
    float w0 = g_l[0][row] * exp2f(m0 - M);
    float w1 = g_l[1][row] * exp2f(m1 - M);
    int col = idx & (DD - 1);
    out[idx] = (w0 * g_opart[0][row][col] + w1 * g_opart[1][row][col]) / (w0 + w1);
}

extern "C" void kernel_launch(void* const* d_in, const int* in_sizes, int n_in,
                              void* d_out, int out_size)
{
    const float* p1 = (const float*)d_in[0];
    const float* p2 = (const float*)d_in[1];
    float* out = (float*)d_out;

    const int smem_bytes = SMEM_FLOATS * (int)sizeof(float);
    cudaFuncSetAttribute(attn_fwd_kernel,
                         cudaFuncAttributeMaxDynamicSharedMemorySize, smem_bytes);

    attn_fwd_kernel<<<(N1v / BM) * 2, NTHREADS, smem_bytes>>>(p1, p2);
    merge_kernel<<<(N1v * DD) / 256, 256>>>(out);
}

// round 9
// speedup vs baseline: 1.1970x; 1.1970x over previous
#include <cuda_runtime.h>
#include <math_constants.h>

// out = softmax(p1 @ p2^T * sqrt(N2)) @ p2 ; N1=N2=8192, D=128, fp32.
//
// Round 9: R6 structure (BN=64, sync tile loads, 2 CTAs/SM, split-KV x2)
// + instruction diet only:
//   * P stored packed-duplicated {p,p} -> GEMM2 loses all PACK2 ALU ops
//   * deferred l-sum (lane-local, one 16-lane butterfly at kernel end)
//   * ex2.approx.ftz.f32 for all exponentials
// (R8's BN=32 + cp.async restructure REGRESSED: per-tile barrier+shfl serial
//  overhead doubled. Reverted.)

#define N1v 8192
#define N2v 8192
#define DD  128
#define BM  64
#define BN  64
#define NKV_HALF 4096
#define KVPAD 132   // q/kv row stride (floats)
#define PPAD  132   // sp row stride (floats): 128 dup floats + pad
#define NTHREADS 256
#define C2F 130.57784f   // sqrt(8192) * log2(e)

// packed f32x2 ops (ptxas never auto-fuses these from C++)
#define FMA2(d, a, b) asm("fma.rn.f32x2 %0, %1, %2, %0;" : "+l"(d) : "l"(a), "l"(b))
#define MUL2(d, s)    asm("mul.rn.f32x2 %0, %0, %1;"     : "+l"(d) : "l"(s))
#define PACK2(d, x, y) asm("mov.b64 %0, {%1, %2};" : "=l"(d) : "f"(x), "f"(y))
#define UNPACK2(lo, hi, v) asm("mov.b64 {%0, %1}, %2;" : "=f"(lo), "=f"(hi) : "l"(v))

__device__ __forceinline__ float ex2(float x) {
    float r;
    asm("ex2.approx.ftz.f32 %0, %1;" : "=f"(r) : "f"(x));
    return r;
}

// ---- split-KV scratch (static device globals: no runtime allocation) ----
__device__ float g_opart[2][N1v][DD];
__device__ float g_m[2][N1v];
__device__ float g_l[2][N1v];

__global__ __launch_bounds__(NTHREADS, 2)
void attn_fwd_kernel(const float* __restrict__ P1,
                     const float* __restrict__ P2)
{
    extern __shared__ float smem[];
    float* sq  = smem;                      // [BM][KVPAD]
    float* skv = sq  + BM * KVPAD;          // [BN][KVPAD]
    float* sp  = skv + BN * KVPAD;          // [BM][PPAD]  (dup pairs, 128 floats)

    const int t   = threadIdx.x;
    const int mr  = t >> 4;                 // 0..15 row-group id
    const int mc  = t & 15;                 // 0..15 lane within row-group
    const int r0  = mr * 4;                 // this thread's 4 score/output rows
    const int dcA = 4 * mc;                 // GEMM2 output cols {4mc..4mc+3}
    const int dcB = 64 + 4 * mc;            //                  {64+4mc..}
    const int qt    = blockIdx.x >> 1;
    const int half  = blockIdx.x & 1;
    const int qbase = qt * BM;
    const int kv0   = half * NKV_HALF;

    // ---- load Q tile (BM x 128 floats = 2048 float4, 8 per thread) ----
    {
        const float4* src = (const float4*)(P1 + (size_t)qbase * DD);
        #pragma unroll
        for (int i = 0; i < 8; i++) {
            int idx = t + i * NTHREADS;       // 0..2047
            int row = idx >> 5;               // 32 float4 per row
            int c4  = idx & 31;
            float4 v = src[idx];
            *(float4*)&sq[row * KVPAD + c4 * 4] = v;
        }
    }

    // ---- softmax state + packed O accumulators ----
    float m_run[4], l_lane[4];
    unsigned long long o2[4][4];            // 4 rows x 4 col-pairs (8 cols)
    #pragma unroll
    for (int i = 0; i < 4; i++) {
        m_run[i] = -CUDART_INF_F;
        l_lane[i] = 0.f;
        #pragma unroll
        for (int d = 0; d < 4; d++) o2[i][d] = 0ull;
    }

    __syncthreads();

    for (int it = 0; it < NKV_HALF / BN; it++) {
        const int jb = kv0 + it * BN;

        // ---- load KV tile ----
        {
            const float4* src = (const float4*)(P2 + (size_t)jb * DD);
            #pragma unroll
            for (int i = 0; i < 8; i++) {
                int idx = t + i * NTHREADS;
                int row = idx >> 5;
                int c4  = idx & 31;
                float4 v = src[idx];
                *(float4*)&skv[row * KVPAD + c4 * 4] = v;
            }
        }
        __syncthreads();

        // ---- GEMM1 (packed k-pairs): acc2[i][j] = q[r0+i] . kv[mc+16j] ----
        unsigned long long acc2[4][4];
        #pragma unroll
        for (int i = 0; i < 4; i++)
            #pragma unroll
            for (int j = 0; j < 4; j++) acc2[i][j] = 0ull;

        #pragma unroll 2
        for (int k = 0; k < DD; k += 4) {
            ulonglong2 B[4];
            #pragma unroll
            for (int j = 0; j < 4; j++)       // 16 unique rows per warp: 2-cyc min
                B[j] = *(const ulonglong2*)&skv[(mc + 16 * j) * KVPAD + k];
            #pragma unroll
            for (int i = 0; i < 4; i++) {     // A broadcast (2 unique per warp)
                ulonglong2 A = *(const ulonglong2*)&sq[(r0 + i) * KVPAD + k];
                #pragma unroll
                for (int j = 0; j < 4; j++) {
                    FMA2(acc2[i][j], A.x, B[j].x);
                    FMA2(acc2[i][j], A.y, B[j].y);
                }
            }
        }

        // ---- online softmax: max across 16-lane group; l deferred ----
        #pragma unroll
        for (int i = 0; i < 4; i++) {
            float s[4];
            #pragma unroll
            for (int j = 0; j < 4; j++) {
                float lo, hi;
                UNPACK2(lo, hi, acc2[i][j]);
                s[j] = lo + hi;
            }
            float mloc = fmaxf(fmaxf(s[0], s[1]), fmaxf(s[2], s[3])) * C2F;
            #pragma unroll
            for (int off = 1; off < 16; off <<= 1)
                mloc = fmaxf(mloc, __shfl_xor_sync(0xffffffffu, mloc, off));

            float mnew = fmaxf(m_run[i], mloc);
            float corr = ex2(m_run[i] - mnew);   // ex2(-inf)=0 first tile
            m_run[i] = mnew;

            float p[4];
            #pragma unroll
            for (int j = 0; j < 4; j++)
                p[j] = ex2(fmaf(s[j], C2F, -mnew));
            l_lane[i] = fmaf(l_lane[i], corr, (p[0] + p[1]) + (p[2] + p[3]));

            // store duplicated pairs {p,p}: col c -> sp[row*PPAD + 2c]
            #pragma unroll
            for (int j = 0; j < 4; j++) {
                unsigned long long dp;
                PACK2(dp, p[j], p[j]);
                *(unsigned long long*)&sp[(r0 + i) * PPAD + 2 * (mc + 16 * j)] = dp;
            }

            unsigned long long corr2;
            PACK2(corr2, corr, corr);
            #pragma unroll
            for (int d = 0; d < 4; d++) MUL2(o2[i][d], corr2);
        }
        // P rows r0..r0+3 produced & consumed entirely within this 16-lane group
        __syncwarp();

        // ---- GEMM2: o2[i][.] += P[r0+i][j] * kv[j][cols], P pre-packed ----
        #pragma unroll 1
        for (int jb4 = 0; jb4 < BN; jb4 += 4) {
            ulonglong2 Pa[4], Pb[4];   // dup pairs: Pa = j{jb4,jb4+1}, Pb = j{+2,+3}
            #pragma unroll
            for (int i = 0; i < 4; i++) {
                const float* pr = &sp[(r0 + i) * PPAD + 2 * jb4];
                Pa[i] = *(const ulonglong2*)pr;        // broadcast (2 unique/warp)
                Pb[i] = *(const ulonglong2*)(pr + 4);
            }
            #pragma unroll
            for (int jj = 0; jj < 4; jj++) {
                const float* vr = &skv[(jb4 + jj) * KVPAD];
                ulonglong2 vA = *(const ulonglong2*)(vr + dcA);
                ulonglong2 vB = *(const ulonglong2*)(vr + dcB);
                #pragma unroll
                for (int i = 0; i < 4; i++) {
                    unsigned long long pp =
                        (jj == 0) ? Pa[i].x : (jj == 1) ? Pa[i].y
                      : (jj == 2) ? Pb[i].x : Pb[i].y;
                    FMA2(o2[i][0], pp, vA.x);
                    FMA2(o2[i][1], pp, vA.y);
                    FMA2(o2[i][2], pp, vB.x);
                    FMA2(o2[i][3], pp, vB.y);
                }
            }
        }
        __syncthreads();   // before next tile overwrites skv
    }

    // ---- finalize l: one butterfly over the 16-lane row group ----
    float l_run[4];
    #pragma unroll
    for (int i = 0; i < 4; i++) {
        float l = l_lane[i];
        #pragma unroll
        for (int off = 1; off < 16; off <<= 1)
            l += __shfl_xor_sync(0xffffffffu, l, off);
        l_run[i] = l;
    }

    // ---- epilogue: per-half normalized partial + (m,l) for the merge ----
    if (mc == 0) {
        #pragma unroll
        for (int i = 0; i < 4; i++) {
            g_m[half][qbase + r0 + i] = m_run[i];
            g_l[half][qbase + r0 + i] = l_run[i];
        }
    }
    #pragma unroll
    for (int i = 0; i < 4; i++) {
        float inv = 1.0f / l_run[i];
        float f[8];
        #pragma unroll
        for (int d = 0; d < 4; d++) {
            float lo, hi;
            UNPACK2(lo, hi, o2[i][d]);
            f[2 * d]     = lo * inv;
            f[2 * d + 1] = hi * inv;
        }
        float* dst = &g_opart[half][qbase + r0 + i][0];
        *(float4*)(dst + dcA) = make_float4(f[0], f[1], f[2], f[3]);
        *(float4*)(dst + dcB) = make_float4(f[4], f[5], f[6], f[7]);
    }
}

// combine the two KV halves:  out = (w0*o0 + w1*o1)/(w0+w1),  w = l * 2^(m-M)
__global__ void merge_kernel(float* __restrict__ out)
{
    int idx = blockIdx.x * blockDim.x + threadIdx.x;   // over 8192*128
    int row = idx >> 7;
    float m0 = g_m[0][row], m1 = g_m[1][row];
    float M  = fmaxf(m0, m1);
    float w0 = g_l[0][row] * exp2f(m0 - M);
    float w1 = g_l[1][row] * exp2f(m1 - M);
    int col = idx & (DD - 1);
    out[idx] = (w0 * g_opart[0][row][col] + w1 * g_opart[1][row][col]) / (w0 + w1);
}

extern "C" void kernel_launch(void* const* d_in, const int* in_sizes, int n_in,
                              void* d_out, int out_size)
{
    const float* p1 = (const float*)d_in[0];
    const float* p2 = (const float*)d_in[1];
    float* out = (float*)d_out;

    const int smem_bytes = (BM * KVPAD + BN * KVPAD + BM * PPAD) * (int)sizeof(float);
    cudaFuncSetAttribute(attn_fwd_kernel,
                         cudaFuncAttributeMaxDynamicSharedMemorySize, smem_bytes);

    attn_fwd_kernel<<<(N1v / BM) * 2, NTHREADS, smem_bytes>>>(p1, p2);
    merge_kernel<<<(N1v * DD) / 256, 256>>>(out);
}

// round 10
// speedup vs baseline: 1.4895x; 1.2443x over previous
#include <cuda_runtime.h>
#include <math_constants.h>

// out = softmax(p1 @ p2^T * sqrt(N2)) @ p2 ; N1=N2=8192, D=128, fp32.
//
// Round 10: R6 compute core (BN=64, plain P + PACK2 GEMM2, sync tile loads,
// 2 CTAs/SM) + load-balance fix:
//   * grid = 296 = 2 x 148 SMs exactly; split-KV x8 -> 1024 jobs of 16
//     KV-tiles, static round-robin (job = blockIdx.x + k*296).
//     Worst-case SM load drops 128 -> 112 tile-times.
//   * deferred lane-local l-sum + ex2.approx.ftz kept (cheap, exact/1-ulp).
//   * R9's dup-P store REVERTED (doubled STS bytes for no alu savings).

#define N1v 8192
#define N2v 8192
#define DD  128
#define BM  64
#define BN  64
#define NSPLIT 8
#define NKV_JOB (N2v / NSPLIT)       // 1024 rows per job
#define NT_JOB  (NKV_JOB / BN)       // 16 tiles per job
#define NJOBS   ((N1v / BM) * NSPLIT)  // 1024
#define GRID    296                  // 2 CTAs x 148 SMs
#define KVPAD 132
#define PPAD  68
#define NTHREADS 256
#define C2F 130.57784f               // sqrt(8192) * log2(e)

// packed f32x2 ops (ptxas never auto-fuses these from C++)
#define FMA2(d, a, b) asm("fma.rn.f32x2 %0, %1, %2, %0;" : "+l"(d) : "l"(a), "l"(b))
#define MUL2(d, s)    asm("mul.rn.f32x2 %0, %0, %1;"     : "+l"(d) : "l"(s))
#define PACK2(d, x, y) asm("mov.b64 %0, {%1, %2};" : "=l"(d) : "f"(x), "f"(y))
#define UNPACK2(lo, hi, v) asm("mov.b64 {%0, %1}, %2;" : "=f"(lo), "=f"(hi) : "l"(v))

__device__ __forceinline__ float ex2(float x) {
    float r;
    asm("ex2.approx.ftz.f32 %0, %1;" : "=f"(r) : "f"(x));
    return r;
}

// ---- split-KV scratch (static device globals: no runtime allocation) ----
__device__ float g_opart[NSPLIT][N1v][DD];
__device__ float g_m[NSPLIT][N1v];
__device__ float g_l[NSPLIT][N1v];

__global__ __launch_bounds__(NTHREADS, 2)
void attn_fwd_kernel(const float* __restrict__ P1,
                     const float* __restrict__ P2)
{
    extern __shared__ float smem[];
    float* sq  = smem;                      // [BM][KVPAD]
    float* skv = sq  + BM * KVPAD;          // [BN][KVPAD]
    float* sp  = skv + BN * KVPAD;          // [BM][PPAD]

    const int t   = threadIdx.x;
    const int mr  = t >> 4;                 // 0..15 row-group id
    const int mc  = t & 15;                 // 0..15 lane within row-group
    const int r0  = mr * 4;                 // this thread's 4 score/output rows
    const int dcA = 4 * mc;                 // GEMM2 output cols {4mc..4mc+3}
    const int dcB = 64 + 4 * mc;            //                  {64+4mc..}

    for (int job = blockIdx.x; job < NJOBS; job += GRID) {
        const int qt    = job >> 3;          // q-tile index 0..127
        const int s     = job & (NSPLIT - 1);
        const int qbase = qt * BM;
        const int kv0   = s * NKV_JOB;

        // ---- load Q tile (BM x 128 floats = 2048 float4, 8 per thread) ----
        {
            const float4* src = (const float4*)(P1 + (size_t)qbase * DD);
            #pragma unroll
            for (int i = 0; i < 8; i++) {
                int idx = t + i * NTHREADS;   // 0..2047
                int row = idx >> 5;           // 32 float4 per row
                int c4  = idx & 31;
                float4 v = src[idx];
                *(float4*)&sq[row * KVPAD + c4 * 4] = v;
            }
        }

        // ---- softmax state + packed O accumulators ----
        float m_run[4], l_lane[4];
        unsigned long long o2[4][4];
        #pragma unroll
        for (int i = 0; i < 4; i++) {
            m_run[i] = -CUDART_INF_F;
            l_lane[i] = 0.f;
            #pragma unroll
            for (int d = 0; d < 4; d++) o2[i][d] = 0ull;
        }

        __syncthreads();   // sq ready (and previous job fully done with smem)

        for (int it = 0; it < NT_JOB; it++) {
            const int jb = kv0 + it * BN;

            // ---- load KV tile ----
            {
                const float4* src = (const float4*)(P2 + (size_t)jb * DD);
                #pragma unroll
                for (int i = 0; i < 8; i++) {
                    int idx = t + i * NTHREADS;
                    int row = idx >> 5;
                    int c4  = idx & 31;
                    float4 v = src[idx];
                    *(float4*)&skv[row * KVPAD + c4 * 4] = v;
                }
            }
            __syncthreads();

            // ---- GEMM1 (packed k-pairs): acc2[i][j] = q[r0+i] . kv[mc+16j] ----
            unsigned long long acc2[4][4];
            #pragma unroll
            for (int i = 0; i < 4; i++)
                #pragma unroll
                for (int j = 0; j < 4; j++) acc2[i][j] = 0ull;

            #pragma unroll 2
            for (int k = 0; k < DD; k += 4) {
                ulonglong2 B[4];
                #pragma unroll
                for (int j = 0; j < 4; j++)   // 16 unique 16B chunks: 2-phase floor
                    B[j] = *(const ulonglong2*)&skv[(mc + 16 * j) * KVPAD + k];
                #pragma unroll
                for (int i = 0; i < 4; i++) { // broadcast (2 unique per warp)
                    ulonglong2 A = *(const ulonglong2*)&sq[(r0 + i) * KVPAD + k];
                    #pragma unroll
                    for (int j = 0; j < 4; j++) {
                        FMA2(acc2[i][j], A.x, B[j].x);
                        FMA2(acc2[i][j], A.y, B[j].y);
                    }
                }
            }

            // ---- online softmax: max across 16-lane group; l deferred ----
            #pragma unroll
            for (int i = 0; i < 4; i++) {
                float sv[4];
                #pragma unroll
                for (int j = 0; j < 4; j++) {
                    float lo, hi;
                    UNPACK2(lo, hi, acc2[i][j]);
                    sv[j] = lo + hi;
                }
                float mloc = fmaxf(fmaxf(sv[0], sv[1]), fmaxf(sv[2], sv[3])) * C2F;
                #pragma unroll
                for (int off = 1; off < 16; off <<= 1)
                    mloc = fmaxf(mloc, __shfl_xor_sync(0xffffffffu, mloc, off));

                float mnew = fmaxf(m_run[i], mloc);
                float corr = ex2(m_run[i] - mnew);   // ex2(-inf)=0 first tile
                m_run[i] = mnew;

                float p[4];
                #pragma unroll
                for (int j = 0; j < 4; j++) {
                    p[j] = ex2(fmaf(sv[j], C2F, -mnew));
                    sp[(r0 + i) * PPAD + mc + 16 * j] = p[j];
                }
                l_lane[i] = fmaf(l_lane[i], corr, (p[0] + p[1]) + (p[2] + p[3]));

                unsigned long long corr2;
                PACK2(corr2, corr, corr);
                #pragma unroll
                for (int d = 0; d < 4; d++) MUL2(o2[i][d], corr2);
            }
            // P rows r0..r0+3 produced & consumed within this 16-lane group
            __syncwarp();

            // ---- GEMM2: o2[i][.] += P[r0+i][j] * kv[j][cols] ----
            #pragma unroll 1
            for (int jb4 = 0; jb4 < BN; jb4 += 4) {
                float4 P4[4];
                #pragma unroll
                for (int i = 0; i < 4; i++)   // broadcast (2 unique addrs/warp)
                    P4[i] = *(const float4*)&sp[(r0 + i) * PPAD + jb4];
                #pragma unroll
                for (int jj = 0; jj < 4; jj++) {
                    const float* vr = &skv[(jb4 + jj) * KVPAD];
                    ulonglong2 vA = *(const ulonglong2*)(vr + dcA);
                    ulonglong2 vB = *(const ulonglong2*)(vr + dcB);
                    #pragma unroll
                    for (int i = 0; i < 4; i++) {
                        float pv = ((const float*)&P4[i])[jj];
                        unsigned long long pp;
                        PACK2(pp, pv, pv);
                        FMA2(o2[i][0], pp, vA.x);
                        FMA2(o2[i][1], pp, vA.y);
                        FMA2(o2[i][2], pp, vB.x);
                        FMA2(o2[i][3], pp, vB.y);
                    }
                }
            }
            __syncthreads();   // before next tile overwrites skv
        }

        // ---- finalize l: one butterfly over the 16-lane row group ----
        float l_run[4];
        #pragma unroll
        for (int i = 0; i < 4; i++) {
            float l = l_lane[i];
            #pragma unroll
            for (int off = 1; off < 16; off <<= 1)
                l += __shfl_xor_sync(0xffffffffu, l, off);
            l_run[i] = l;
        }

        // ---- epilogue: per-split normalized partial + (m,l) ----
        if (mc == 0) {
            #pragma unroll
            for (int i = 0; i < 4; i++) {
                g_m[s][qbase + r0 + i] = m_run[i];
                g_l[s][qbase + r0 + i] = l_run[i];
            }
        }
        #pragma unroll
        for (int i = 0; i < 4; i++) {
            float inv = 1.0f / l_run[i];
            float f[8];
            #pragma unroll
            for (int d = 0; d < 4; d++) {
                float lo, hi;
                UNPACK2(lo, hi, o2[i][d]);
                f[2 * d]     = lo * inv;
                f[2 * d + 1] = hi * inv;
            }
            float* dst = &g_opart[s][qbase + r0 + i][0];
            *(float4*)(dst + dcA) = make_float4(f[0], f[1], f[2], f[3]);
            *(float4*)(dst + dcB) = make_float4(f[4], f[5], f[6], f[7]);
        }
        // next job's Q-load writes sq only after loop-top __syncthreads
    }
}

// combine the NSPLIT KV splits:  out = sum_s w_s*o_s / sum_s w_s, w = l*2^(m-M)
__global__ void merge_kernel(float* __restrict__ out)
{
    int idx = blockIdx.x * blockDim.x + threadIdx.x;   // over 8192*128
    int row = idx >> 7;
    int col = idx & (DD - 1);

    float m[NSPLIT];
    float M = -CUDART_INF_F;
    #pragma unroll
    for (int s = 0; s < NSPLIT; s++) {
        m[s] = g_m[s][row];
        M = fmaxf(M, m[s]);
    }
    float wsum = 0.f, acc = 0.f;
    #pragma unroll
    for (int s = 0; s < NSPLIT; s++) {
        float w = g_l[s][row] * exp2f(m[s] - M);
        acc  = fmaf(w, g_opart[s][row][col], acc);
        wsum += w;
    }
    out[idx] = acc / wsum;
}

extern "C" void kernel_launch(void* const* d_in, const int* in_sizes, int n_in,
                              void* d_out, int out_size)
{
    const float* p1 = (const float*)d_in[0];
    const float* p2 = (const float*)d_in[1];
    float* out = (float*)d_out;

    const int smem_bytes = (BM * KVPAD + BN * KVPAD + BM * PPAD) * (int)sizeof(float);
    cudaFuncSetAttribute(attn_fwd_kernel,
                         cudaFuncAttributeMaxDynamicSharedMemorySize, smem_bytes);

    attn_fwd_kernel<<<GRID, NTHREADS, smem_bytes>>>(p1, p2);
    merge_kernel<<<(N1v * DD) / 256, 256>>>(out);
}